// round 3
// baseline (speedup 1.0000x reference)
#include <cuda_runtime.h>
#include <cuda_bf16.h>

// LabelClusterLoss over E[C0=512, T=128, C1=1024] fp32, single fused kernel.
// Four streaming accumulators:
//   A_sq = sum(E^2)
//   A_R2 = sum over rows (i,t) of (rowsum over j)^2
//   A_C2 = sum over (t,j) of (colsum over i)^2
//   A_T2 = sum over t of (total slice-t sum)^2
//
// Grid = 256 blocks: block b -> (t = b>>1, row-half h = b&1). 512 thr = 16 warps.
// Per-t combine elected via counter (second finisher), global finalize elected
// via counter (last of 128 combiners). All counters self-reset -> deterministic,
// no init kernel, graph-capturable, no allocations.

#define T_DIM 128
#define C0_DIM 512
#define C1_DIM 1024
#define NBLK (T_DIM * 2)

__device__ float        part_cs[T_DIM][2][C1_DIM];  // per-(t,half) colsum partials (1 MB)
__device__ float        part_sr[T_DIM][2][2];       // per-(t,half) {sq, r2}
__device__ double       out_t[T_DIM][4];            // per-t {sq, r2, cs2, cs^2}
__device__ unsigned int t_count[T_DIM];             // zero at load; reset each run
__device__ unsigned int g_count;                    // zero at load; reset each run

__global__ void __launch_bounds__(512, 2)
label_cluster_fused(const float* __restrict__ A, float* __restrict__ out) {
    const int b    = blockIdx.x;
    const int t    = b >> 1;
    const int h    = b & 1;
    const int tid  = threadIdx.x;
    const int w    = tid >> 5;
    const int lane = tid & 31;

    // ---- Streaming pass: rows h*256 .. h*256+255 of slice t ----
    float colsum[32];
#pragma unroll
    for (int q = 0; q < 32; q++) colsum[q] = 0.0f;
    float sq_acc = 0.0f;
    float r2_acc = 0.0f;   // lane 0 only

    const int row_base = h * 256;
    for (int k = 0; k < 16; k++) {
        const int i = row_base + w + 16 * k;
        const float4* row =
            reinterpret_cast<const float4*>(A + ((size_t)i * T_DIM + t) * C1_DIM) + lane;
        float rs = 0.0f;
#pragma unroll
        for (int p = 0; p < 8; p++) {
            float4 v = row[p * 32];   // 512B contiguous per warp per load
            sq_acc = fmaf(v.x, v.x, sq_acc);
            sq_acc = fmaf(v.y, v.y, sq_acc);
            sq_acc = fmaf(v.z, v.z, sq_acc);
            sq_acc = fmaf(v.w, v.w, sq_acc);
            colsum[p * 4 + 0] += v.x;
            colsum[p * 4 + 1] += v.y;
            colsum[p * 4 + 2] += v.z;
            colsum[p * 4 + 3] += v.w;
            rs += (v.x + v.y) + (v.z + v.w);
        }
#pragma unroll
        for (int o = 16; o > 0; o >>= 1) rs += __shfl_xor_sync(0xFFFFFFFFu, rs, o);
        if (lane == 0) r2_acc = fmaf(rs, rs, r2_acc);
    }

    // ---- Cross-warp colsum tree (16 warps -> warp 0), 32 KB smem ----
    __shared__ float sbuf[8 * 1024];
    struct Round { int src, dst, n; };
    const Round rounds[4] = { {8,0,8}, {4,0,4}, {2,0,2}, {1,0,1} };
#pragma unroll
    for (int r = 0; r < 4; r++) {
        const int src = rounds[r].src, dst = rounds[r].dst, n = rounds[r].n;
        if (w >= src && w < src + n) {
            float* dstp = &sbuf[(w - src) * 1024];
#pragma unroll
            for (int p = 0; p < 8; p++)
                reinterpret_cast<float4*>(dstp)[p * 32 + lane] =
                    make_float4(colsum[p*4+0], colsum[p*4+1], colsum[p*4+2], colsum[p*4+3]);
        }
        __syncthreads();
        if (w >= dst && w < dst + n) {
            const float* srcp = &sbuf[(w - dst) * 1024];
#pragma unroll
            for (int p = 0; p < 8; p++) {
                float4 u = reinterpret_cast<const float4*>(srcp)[p * 32 + lane];
                colsum[p*4+0] += u.x; colsum[p*4+1] += u.y;
                colsum[p*4+2] += u.z; colsum[p*4+3] += u.w;
            }
        }
        __syncthreads();
    }

    // ---- Block totals of sq / r2 ----
    __shared__ float warp_a[16];
    __shared__ float warp_b[16];
    {
        float s = sq_acc;
#pragma unroll
        for (int o = 16; o > 0; o >>= 1) s += __shfl_xor_sync(0xFFFFFFFFu, s, o);
        if (lane == 0) { warp_a[w] = s; warp_b[w] = r2_acc; }
    }
    __syncthreads();

    if (w == 0) {
        float bsq = (lane < 16) ? warp_a[lane] : 0.0f;
        float br2 = (lane < 16) ? warp_b[lane] : 0.0f;
#pragma unroll
        for (int o = 8; o > 0; o >>= 1) {
            bsq += __shfl_xor_sync(0xFFFFFFFFu, bsq, o);
            br2 += __shfl_xor_sync(0xFFFFFFFFu, br2, o);
        }
        if (lane == 0) { part_sr[t][h][0] = bsq; part_sr[t][h][1] = br2; }
        // warp 0 holds the half-colsum: write 1024 floats to staging
        float4* dst = reinterpret_cast<float4*>(&part_cs[t][h][0]);
#pragma unroll
        for (int p = 0; p < 8; p++)
            dst[p * 32 + lane] =
                make_float4(colsum[p*4+0], colsum[p*4+1], colsum[p*4+2], colsum[p*4+3]);
    }

    // ---- Elect second finisher for this t ----
    __shared__ bool s_second;
    __shared__ bool s_final;
    __syncthreads();                 // staging writes done block-wide
    if (tid == 0) {
        s_final = false;
        __threadfence();
        unsigned old = atomicAdd(&t_count[t], 1);
        s_second = (old == 1);
    }
    __syncthreads();

    if (s_second) {
        __threadfence();
        // combine halves: 512 threads x 2 columns each
        float f0 = __ldcg(&part_cs[t][0][tid])       + __ldcg(&part_cs[t][1][tid]);
        float f1 = __ldcg(&part_cs[t][0][tid + 512]) + __ldcg(&part_cs[t][1][tid + 512]);
        float cs  = f0 + f1;
        float cs2 = fmaf(f0, f0, f1 * f1);
#pragma unroll
        for (int o = 16; o > 0; o >>= 1) {
            cs  += __shfl_xor_sync(0xFFFFFFFFu, cs,  o);
            cs2 += __shfl_xor_sync(0xFFFFFFFFu, cs2, o);
        }
        if (lane == 0) { warp_a[w] = cs; warp_b[w] = cs2; }
        __syncthreads();
        if (tid == 0) {
            float tcs = 0.0f, tcs2 = 0.0f;
#pragma unroll
            for (int q = 0; q < 16; q++) { tcs += warp_a[q]; tcs2 += warp_b[q]; }
            double sq_t = (double)__ldcg(&part_sr[t][0][0]) + (double)__ldcg(&part_sr[t][1][0]);
            double r2_t = (double)__ldcg(&part_sr[t][0][1]) + (double)__ldcg(&part_sr[t][1][1]);
            out_t[t][0] = sq_t;
            out_t[t][1] = r2_t;
            out_t[t][2] = (double)tcs2;
            out_t[t][3] = (double)tcs * (double)tcs;
            t_count[t] = 0;                      // self-reset for next launch
            __threadfence();
            unsigned o2 = atomicAdd(&g_count, 1);
            if (o2 == T_DIM - 1) s_final = true;
        }
    }
    __syncthreads();

    // ---- Last combiner computes the loss ----
    if (s_final) {
        __threadfence();
        if (w == 0) {
            double a0 = 0, a1 = 0, a2 = 0, a3 = 0;
#pragma unroll
            for (int q = 0; q < 4; q++) {
                int tt = lane + 32 * q;
                a0 += __ldcg(&out_t[tt][0]);
                a1 += __ldcg(&out_t[tt][1]);
                a2 += __ldcg(&out_t[tt][2]);
                a3 += __ldcg(&out_t[tt][3]);
            }
#pragma unroll
            for (int o = 16; o > 0; o >>= 1) {
                a0 += __shfl_xor_sync(0xFFFFFFFFu, a0, o);
                a1 += __shfl_xor_sync(0xFFFFFFFFu, a1, o);
                a2 += __shfl_xor_sync(0xFFFFFFFFu, a2, o);
                a3 += __shfl_xor_sync(0xFFFFFFFFu, a3, o);
            }
            if (lane == 0) {
                const double c0 = (double)C0_DIM, c1 = (double)C1_DIM;
                const double cross  = a3 / (c0 * c1);
                const double intra  = a0 - a1 / c1;
                const double inter  = a1 / c1 - cross;
                const double dintra = a0 - a2 / c0;
                const double dinter = a2 / c0 - cross;
                out[0] = (float)(0.5 * (intra / inter + dintra / dinter) / (c0 * c1));
                g_count = 0;                     // self-reset for next launch
            }
        }
    }
}

extern "C" void kernel_launch(void* const* d_in, const int* in_sizes, int n_in,
                              void* d_out, int out_size) {
    const float* A = (const float*)d_in[0];
    float* out = (float*)d_out;
    (void)in_sizes; (void)n_in; (void)out_size;

    label_cluster_fused<<<NBLK, 512>>>(A, out);
}